// round 3
// baseline (speedup 1.0000x reference)
#include <cuda_runtime.h>
#include <math.h>

#define FULLMASK 0xFFFFFFFFu

// ---------------- static device scratch (no allocation) ----------------
__device__ float d_La[1024];        // alpha logits (batch-constant)
__device__ float d_c1[128];         // baseline_b @ W1b[:1024] + b1b
__device__ float d_ctx[8192 * 32];  // per-row context after alpha selection

__device__ __forceinline__ float leaky(float x) { return x >= 0.f ? x : 0.01f * x; }

// order-preserving float -> unsigned key (monotone bijection on non-NaN)
__device__ __forceinline__ unsigned f2ord(float f) {
    unsigned u = __float_as_uint(f);
    return u ^ (unsigned)(((int)u >> 31) | 0x80000000);
}

static __device__ __forceinline__ unsigned long long pack2(float x, float y) {
    unsigned long long r;
    asm("mov.b64 %0, {%1, %2};" : "=l"(r) : "f"(x), "f"(y));
    return r;
}
static __device__ __forceinline__ void unpack2(unsigned long long v, float& x, float& y) {
    asm("mov.b64 {%0, %1}, %2;" : "=f"(x), "=f"(y) : "l"(v));
}
static __device__ __forceinline__ unsigned long long fma2(unsigned long long a,
                                                          unsigned long long b,
                                                          unsigned long long c) {
    unsigned long long d;
    asm("fma.rn.f32x2 %0, %1, %2, %3;" : "=l"(d) : "l"(a), "l"(b), "l"(c));
    return d;
}

// ---------------- warp top-32-of-1024 on ordered uint keys ----------------
// Lane owns keys v[j] <-> global index j*32 + lane. All real keys are
// >= 0x00800000 (ordered(-maxfloat)), so 0 is a safe "consumed" sentinel.
// Iterative warp argmax: single REDUX.SYNC.MAX.U32 per round, lazy per-lane
// top-2 with masked rescan only when both cached candidates are consumed.
template <bool WANT_IDX>
__device__ __forceinline__ unsigned warp_select32(const unsigned* v, int lane, int* my_gidx) {
    unsigned m1 = 0, m2 = 0;
    int i1 = 0, i2 = 0;
#pragma unroll
    for (int j = 0; j < 32; j++) {
        unsigned x = v[j];
        if (x > m1) { m2 = m1; i2 = i1; m1 = x; i1 = j; }
        else if (x > m2) { m2 = x; i2 = j; }
    }
    unsigned sel = 0;
#pragma unroll 1
    for (int k = 0; k < 32; k++) {
        unsigned best = __reduce_max_sync(FULLMASK, m1);
        unsigned bal = __ballot_sync(FULLMASK, m1 == best);
        int wl = __ffs(bal) - 1;
        if (WANT_IDX) {
            int wj = __shfl_sync(FULLMASK, i1, wl);
            if (lane == k) *my_gidx = wj * 32 + wl;
        }
        if (lane == wl) {
            sel |= 1u << i1;
            m1 = m2; i1 = i2;
            m2 = 0; i2 = 0;
            if (m1 == 0) {  // both cached candidates consumed: masked rescan
#pragma unroll
                for (int j = 0; j < 32; j++) {
                    if (!((sel >> j) & 1)) {
                        unsigned x = v[j];
                        if (x > m1) { m2 = m1; i2 = i1; m1 = x; i1 = j; }
                        else if (x > m2) { m2 = x; i2 = j; }
                    }
                }
            }
        }
    }
    return sel;
}

// ---------------- K1: precompute La and c1 — 1 block x 1024 threads ----------------
// Each 128-wide matvec output is split over 8 threads (smem reduction) so all
// 32 warps keep high MLP with coalesced loads.
__global__ __launch_bounds__(1024) void kprec(
        const float* __restrict__ ba,
        const float* __restrict__ W1a, const float* __restrict__ b1a,
        const float* __restrict__ W2a, const float* __restrict__ b2a,
        const float* __restrict__ W3a, const float* __restrict__ b3a,
        const float* __restrict__ bb,
        const float* __restrict__ W1b, const float* __restrict__ b1b) {
    __shared__ float red[1024];
    __shared__ float redb[1024];
    __shared__ float h1[128];
    __shared__ float h2[64];
    int t = threadIdx.x;
    int o = t & 127, c = t >> 7;  // output, chunk(0..7)

    // layer-1 alpha and beta-c1 partials (interleaved for MLP)
    {
        float pa = 0.f, pb = 0.f;
        int i0 = c * 128;
#pragma unroll 8
        for (int i = i0; i < i0 + 128; i++) {
            float wa = W1a[i * 128 + o];
            float wb = W1b[i * 128 + o];
            pa += ba[i] * wa;
            pb += bb[i] * wb;
        }
        red[t] = pa;
        redb[t] = pb;
    }
    __syncthreads();
    if (t < 128) {
        float sa = 0.f, sb = 0.f;
#pragma unroll
        for (int k = 0; k < 8; k++) { sa += red[k * 128 + t]; sb += redb[k * 128 + t]; }
        h1[t] = leaky(b1a[t] + sa);
        d_c1[t] = b1b[t] + sb;
    }
    __syncthreads();
    // layer 2: 64 outputs, 16 partials each over 8 inputs
    {
        int o2 = t & 63, c2 = t >> 6;
        float p = 0.f;
#pragma unroll
        for (int k = 0; k < 8; k++) {
            int i = c2 * 8 + k;
            p += h1[i] * W2a[i * 64 + o2];
        }
        red[t] = p;
    }
    __syncthreads();
    if (t < 64) {
        float s = 0.f;
#pragma unroll
        for (int k = 0; k < 16; k++) s += red[k * 64 + t];
        h2[t] = leaky(b2a[t] + s);
    }
    __syncthreads();
    // layer 3: one output per thread, coalesced
    {
        float s = 0.f;
#pragma unroll
        for (int i = 0; i < 64; i++) s += h2[i] * W3a[i * 1024 + t];
        d_La[t] = s + b3a[t] + ba[t];
    }
}

// ---------------- K2: alpha selection + ctx (1 warp / row) ----------------
__global__ __launch_bounds__(256) void kalpha(const float* __restrict__ g_alpha,
                                              const float* __restrict__ Wc,
                                              const float* __restrict__ bc,
                                              float* __restrict__ out, int B) {
    __shared__ float La_s[1024];
    for (int i = threadIdx.x; i < 1024; i += 256) La_s[i] = d_La[i];
    __syncthreads();
    int w = threadIdx.x >> 5, lane = threadIdx.x & 31;
    int row = blockIdx.x * 8 + w;
    if (row >= B) return;
    const float* g = g_alpha + (size_t)row * 1024;
    unsigned v[32];
#pragma unroll
    for (int j = 0; j < 32; j++)
        v[j] = f2ord(La_s[j * 32 + lane] + __ldg(g + j * 32 + lane));
    int gidx = 0;
    unsigned sel = warp_select32<true>(v, lane, &gidx);
    float* o = out + (size_t)row * 2048;
#pragma unroll
    for (int j = 0; j < 32; j++) o[j * 32 + lane] = ((sel >> j) & 1) ? 1.0f : 0.0f;
    // ctx = bc + sum of selected Wc rows (hard alpha_config forward)
    float acc = __ldg(bc + lane);
#pragma unroll
    for (int k = 0; k < 32; k++) {
        int idx = __shfl_sync(FULLMASK, gidx, k);
        acc += __ldg(Wc + (size_t)idx * 32 + lane);
    }
    d_ctx[row * 32 + lane] = acc;
}

// ---------------- K3: beta MLP (f32x2 layer 3) + selection, 16 rows/block ----------------
// dyn smem floats: ctx_s[512] | h1s[2048] | h2t[1024] | lg[16384]  (79872 B)
__global__ __launch_bounds__(256, 2) void kbeta(const float* __restrict__ g_beta,
                                                const float* __restrict__ W1b,
                                                const float* __restrict__ W2b,
                                                const float* __restrict__ b2b,
                                                const float* __restrict__ W3b,
                                                const float* __restrict__ b3b,
                                                const float* __restrict__ baseline_b,
                                                float* __restrict__ out, int B) {
    extern __shared__ float sm[];
    float* ctx_s = sm;           // 16 x 32
    float* h1s   = sm + 512;     // 16 x 128
    float* h2t   = sm + 2560;    // 64 x 16  ([o][row])
    float* lg    = sm + 3584;    // 16 x 1024
    int t = threadIdx.x;
    int row0 = blockIdx.x * 16;
    if (row0 >= B) return;

    ctx_s[t]       = d_ctx[row0 * 32 + t];
    ctx_s[256 + t] = d_ctx[row0 * 32 + 256 + t];
    __syncthreads();

    int r = t >> 4, s = t & 15;
    // layer 1: only the 32 ctx rows of W1b matter (base_b folded into d_c1)
    {
        float acc[8];
#pragma unroll
        for (int k = 0; k < 8; k++) acc[k] = d_c1[s + 16 * k];
        for (int i = 0; i < 32; i++) {
            float cv = ctx_s[r * 32 + i];
#pragma unroll
            for (int k = 0; k < 8; k++)
                acc[k] += cv * __ldg(&W1b[(1024 + i) * 128 + s + 16 * k]);
        }
#pragma unroll
        for (int k = 0; k < 8; k++) h1s[r * 128 + s + 16 * k] = leaky(acc[k]);
    }
    __syncthreads();
    // layer 2
    {
        float acc[4];
#pragma unroll
        for (int k = 0; k < 4; k++) acc[k] = __ldg(&b2b[s + 16 * k]);
        for (int i = 0; i < 128; i++) {
            float hv = h1s[r * 128 + i];
#pragma unroll
            for (int k = 0; k < 4; k++)
                acc[k] += hv * __ldg(&W2b[i * 64 + s + 16 * k]);
        }
#pragma unroll
        for (int k = 0; k < 4; k++) h2t[(s + 16 * k) * 16 + r] = leaky(acc[k]);
    }
    __syncthreads();
    // layer 3: thread owns 4 outputs x 16 rows, rows paired in f32x2
    {
        int o0 = t * 4;
        unsigned long long acc[32];
#pragma unroll
        for (int z = 0; z < 32; z++) acc[z] = 0ull;
#pragma unroll 4
        for (int i = 0; i < 64; i++) {
            float4 wv = __ldg((const float4*)(W3b + i * 1024 + o0));
            unsigned long long w0 = pack2(wv.x, wv.x);
            unsigned long long w1 = pack2(wv.y, wv.y);
            unsigned long long w2 = pack2(wv.z, wv.z);
            unsigned long long w3 = pack2(wv.w, wv.w);
            const float2* hp = (const float2*)(h2t + i * 16);
#pragma unroll
            for (int rp = 0; rp < 8; rp++) {
                float2 h = hp[rp];
                unsigned long long hh = pack2(h.x, h.y);
                acc[rp * 4 + 0] = fma2(w0, hh, acc[rp * 4 + 0]);
                acc[rp * 4 + 1] = fma2(w1, hh, acc[rp * 4 + 1]);
                acc[rp * 4 + 2] = fma2(w2, hh, acc[rp * 4 + 2]);
                acc[rp * 4 + 3] = fma2(w3, hh, acc[rp * 4 + 3]);
            }
        }
        float bq[4];
#pragma unroll
        for (int q = 0; q < 4; q++) bq[q] = __ldg(&b3b[o0 + q]) + __ldg(&baseline_b[o0 + q]);
#pragma unroll
        for (int rp = 0; rp < 8; rp++) {
            float lo0, hi0, lo1, hi1, lo2, hi2, lo3, hi3;
            unpack2(acc[rp * 4 + 0], lo0, hi0);
            unpack2(acc[rp * 4 + 1], lo1, hi1);
            unpack2(acc[rp * 4 + 2], lo2, hi2);
            unpack2(acc[rp * 4 + 3], lo3, hi3);
            float4 lov = make_float4(lo0 + bq[0], lo1 + bq[1], lo2 + bq[2], lo3 + bq[3]);
            float4 hiv = make_float4(hi0 + bq[0], hi1 + bq[1], hi2 + bq[2], hi3 + bq[3]);
            *(float4*)(lg + (rp * 2) * 1024 + o0)     = lov;
            *(float4*)(lg + (rp * 2 + 1) * 1024 + o0) = hiv;
        }
    }
    __syncthreads();
    // selection: 8 warps x 2 rows
    int w = t >> 5, lane = t & 31;
#pragma unroll 1
    for (int rr = w * 2; rr < w * 2 + 2; rr++) {
        const float* g = g_beta + (size_t)(row0 + rr) * 1024;
        unsigned v[32];
#pragma unroll
        for (int j = 0; j < 32; j++)
            v[j] = f2ord(lg[rr * 1024 + j * 32 + lane] + __ldg(g + j * 32 + lane));
        int dummy;
        unsigned sel = warp_select32<false>(v, lane, &dummy);
        float* o = out + (size_t)(row0 + rr) * 2048 + 1024;
#pragma unroll
        for (int j = 0; j < 32; j++) o[j * 32 + lane] = ((sel >> j) & 1) ? 1.0f : 0.0f;
    }
}

// ---------------- launcher ----------------
extern "C" void kernel_launch(void* const* d_in, const int* in_sizes, int n_in,
                              void* d_out, int out_size) {
    const float* baseline_a = (const float*)d_in[0];
    const float* W1a = (const float*)d_in[1];
    const float* b1a = (const float*)d_in[2];
    const float* W2a = (const float*)d_in[3];
    const float* b2a = (const float*)d_in[4];
    const float* W3a = (const float*)d_in[5];
    const float* b3a = (const float*)d_in[6];
    const float* baseline_b = (const float*)d_in[7];
    const float* Wc  = (const float*)d_in[8];
    const float* bc  = (const float*)d_in[9];
    const float* W1b = (const float*)d_in[10];
    const float* b1b = (const float*)d_in[11];
    const float* W2b = (const float*)d_in[12];
    const float* b2b = (const float*)d_in[13];
    const float* W3b = (const float*)d_in[14];
    const float* b3b = (const float*)d_in[15];
    const float* g_alpha = (const float*)d_in[16];
    const float* g_beta  = (const float*)d_in[17];
    float* out = (float*)d_out;

    int B = in_sizes[16] / 1024;
    if (B <= 0) return;
    if (B > 8192) B = 8192;  // scratch capacity

    cudaFuncSetAttribute(kbeta, cudaFuncAttributeMaxDynamicSharedMemorySize, 80 * 1024);

    kprec<<<1, 1024>>>(baseline_a, W1a, b1a, W2a, b2a, W3a, b3a,
                       baseline_b, W1b, b1b);
    kalpha<<<(B + 7) / 8, 256>>>(g_alpha, Wc, bc, out, B);
    kbeta<<<(B + 15) / 16, 256, 19968 * sizeof(float)>>>(
        g_beta, W1b, W2b, b2b, W3b, b3b, baseline_b, out, B);
}

// round 4
// speedup vs baseline: 2.4189x; 2.4189x over previous
#include <cuda_runtime.h>
#include <math.h>

#define FULLMASK 0xFFFFFFFFu

// ---------------- static device scratch (no allocation) ----------------
__device__ float d_La[1024];     // alpha logits (batch-constant)
__device__ float d_c1[128];      // baseline_b @ W1b[:1024] + b1b
__device__ float d_p1[2][8192];  // layer-1 partials (64 chunks x 128) x {alpha, beta}
__device__ float d_h2[64];       // alpha hidden-2

__device__ __forceinline__ float leaky(float x) { return x >= 0.f ? x : 0.01f * x; }

// order-preserving float -> unsigned key (monotone bijection on non-NaN)
__device__ __forceinline__ unsigned f2ord(float f) {
    unsigned u = __float_as_uint(f);
    return u ^ (unsigned)(((int)u >> 31) | 0x80000000);
}

static __device__ __forceinline__ unsigned long long pack2(float x, float y) {
    unsigned long long r;
    asm("mov.b64 %0, {%1, %2};" : "=l"(r) : "f"(x), "f"(y));
    return r;
}
static __device__ __forceinline__ void unpack2(unsigned long long v, float& x, float& y) {
    asm("mov.b64 {%0, %1}, %2;" : "=f"(x), "=f"(y) : "l"(v));
}
static __device__ __forceinline__ unsigned long long fma2(unsigned long long a,
                                                          unsigned long long b,
                                                          unsigned long long c) {
    unsigned long long d;
    asm("fma.rn.f32x2 %0, %1, %2, %3;" : "=l"(d) : "l"(a), "l"(b), "l"(c));
    return d;
}

// sorted top-4 insert (strict >, preserves lowest-j among equals)
__device__ __forceinline__ void ins4(unsigned x, int j,
                                     unsigned& m0, unsigned& m1, unsigned& m2, unsigned& m3,
                                     int& i0, int& i1, int& i2, int& i3) {
    if (x > m3) {
        if (x > m1) {
            if (x > m0) { m3 = m2; i3 = i2; m2 = m1; i2 = i1; m1 = m0; i1 = i0; m0 = x; i0 = j; }
            else        { m3 = m2; i3 = i2; m2 = m1; i2 = i1; m1 = x; i1 = j; }
        } else {
            if (x > m2) { m3 = m2; i3 = i2; m2 = x; i2 = j; }
            else        { m3 = x; i3 = j; }
        }
    }
}

// ---------------- warp top-32-of-1024 on ordered uint keys ----------------
// Lane owns v[j] <-> global index (j>>2)*128 + lane*4 + (j&3)   (float4 layout).
// All real keys >= 0x00800000, so 0 is a safe "consumed" sentinel.
// One REDUX.MAX per round; per-lane lazy top-4 cache -> masked rescan is ~never.
template <bool WANT_IDX>
__device__ __forceinline__ unsigned warp_select32(const unsigned* v, int lane, int* my_gidx) {
    unsigned m0 = 0, m1 = 0, m2 = 0, m3 = 0;
    int i0 = 0, i1 = 0, i2 = 0, i3 = 0;
#pragma unroll
    for (int j = 0; j < 32; j++) ins4(v[j], j, m0, m1, m2, m3, i0, i1, i2, i3);
    unsigned sel = 0;
#pragma unroll 1
    for (int k = 0; k < 32; k++) {
        unsigned best = __reduce_max_sync(FULLMASK, m0);
        unsigned bal = __ballot_sync(FULLMASK, m0 == best);
        int wl = __ffs(bal) - 1;
        if (WANT_IDX) {
            int wj = __shfl_sync(FULLMASK, i0, wl);
            if (lane == k) *my_gidx = (wj >> 2) * 128 + wl * 4 + (wj & 3);
        }
        if (lane == wl) {
            sel |= 1u << i0;
            m0 = m1; i0 = i1; m1 = m2; i1 = i2; m2 = m3; i2 = i3; m3 = 0; i3 = 0;
            if (m0 == 0) {  // all 4 cached consumed (P ~ 0.3%/row): masked rescan
#pragma unroll
                for (int j = 0; j < 32; j++)
                    if (!((sel >> j) & 1)) ins4(v[j], j, m0, m1, m2, m3, i0, i1, i2, i3);
            }
        }
    }
    return sel;
}

// ---------------- kp1: layer-1 partials for alpha-h1 and beta-c1 (64 blocks) ----------------
__global__ __launch_bounds__(256) void kp1(const float* __restrict__ ba,
                                           const float* __restrict__ W1a,
                                           const float* __restrict__ bb,
                                           const float* __restrict__ W1b) {
    int t = threadIdx.x;
    int o = t & 127, sel = t >> 7;
    const float* W = sel ? W1b : W1a;
    const float* xv = sel ? bb : ba;
    int i0 = blockIdx.x * 16;
    float p = 0.f;
#pragma unroll
    for (int k = 0; k < 16; k++) p += xv[i0 + k] * W[(i0 + k) * 128 + o];
    d_p1[sel][blockIdx.x * 128 + o] = p;
}

// ---------------- kp2: reduce partials, layer-2 alpha (1 block) ----------------
__global__ __launch_bounds__(256) void kp2(const float* __restrict__ b1a,
                                           const float* __restrict__ b1b,
                                           const float* __restrict__ W2a,
                                           const float* __restrict__ b2a) {
    __shared__ float h1[128];
    __shared__ float red[256];
    int t = threadIdx.x;
    int o = t & 127, sel = t >> 7;
    const float* p = d_p1[sel];
    float s = 0.f;
#pragma unroll 8
    for (int k = 0; k < 64; k++) s += p[k * 128 + o];
    if (sel == 0) h1[o] = leaky(b1a[o] + s);
    else d_c1[o] = b1b[o] + s;
    __syncthreads();
    int o2 = t & 63, c2 = t >> 6;
    float q = 0.f;
#pragma unroll
    for (int k = 0; k < 32; k++) {
        int i = c2 * 32 + k;
        q += h1[i] * W2a[i * 64 + o2];
    }
    red[t] = q;
    __syncthreads();
    if (t < 64)
        d_h2[t] = leaky(b2a[t] + red[t] + red[64 + t] + red[128 + t] + red[192 + t]);
}

// ---------------- kp3: layer-3 alpha -> La (8 blocks) ----------------
__global__ __launch_bounds__(128) void kp3(const float* __restrict__ W3a,
                                           const float* __restrict__ b3a,
                                           const float* __restrict__ ba) {
    __shared__ float h2s[64];
    int t = threadIdx.x;
    if (t < 64) h2s[t] = d_h2[t];
    __syncthreads();
    int o = blockIdx.x * 128 + t;
    float s = 0.f;
#pragma unroll
    for (int i = 0; i < 64; i++) s += h2s[i] * W3a[i * 1024 + o];
    d_La[o] = s + b3a[o] + ba[o];
}

// ---------------- kmain: fused alpha-select + ctx + beta MLP + beta-select ----------------
// 16 rows/block, 256 threads. dyn smem floats:
//   ctx_s[512] | h1s[2048] | h2t[1024] | La_s[1024] | wbuf[16384]
// wbuf holds {W1b ctx-slice [0,4096), W2b [4096,12288)} during layers 1-2, then
// is reused as lg[16x1024] for the layer-3 epilogue (sync separates the uses).
constexpr int F_CTX = 0;
constexpr int F_H1  = 512;
constexpr int F_H2T = 2560;
constexpr int F_LA  = 3584;
constexpr int F_WB  = 4608;
constexpr int SMEM_FLOATS = 20992;  // 83968 bytes

__global__ __launch_bounds__(256, 2) void kmain(
        const float* __restrict__ g_alpha, const float* __restrict__ g_beta,
        const float* __restrict__ Wc, const float* __restrict__ bc,
        const float* __restrict__ W1b, const float* __restrict__ W2b,
        const float* __restrict__ b2b, const float* __restrict__ W3b,
        const float* __restrict__ b3b, const float* __restrict__ baseline_b,
        float* __restrict__ out, int B) {
    extern __shared__ float sm[];
    float* ctx_s = sm + F_CTX;
    float* h1s   = sm + F_H1;
    float* h2t   = sm + F_H2T;
    float* La_s  = sm + F_LA;
    float* wbuf  = sm + F_WB;   // W1b slice / W2b
    float* lg    = wbuf;        // alias, used after layer 2
    int t = threadIdx.x;
    int row0 = blockIdx.x * 16;
    if (row0 >= B) return;

    for (int x = t; x < 1024; x += 256) La_s[x] = d_La[x];
    for (int x = t; x < 4096; x += 256) wbuf[x] = W1b[131072 + x];       // rows 1024..1055
    for (int x = t; x < 8192; x += 256) wbuf[4096 + x] = W2b[x];
    __syncthreads();

    int w = t >> 5, lane = t & 31;
    // ---- alpha: 2 rows per warp ----
#pragma unroll 1
    for (int rr = w * 2; rr < w * 2 + 2; rr++) {
        int row = row0 + rr;
        if (row >= B) { ctx_s[rr * 32 + lane] = 0.f; continue; }
        const float* g = g_alpha + (size_t)row * 1024;
        unsigned v[32];
#pragma unroll
        for (int j4 = 0; j4 < 8; j4++) {
            float4 gv = __ldg((const float4*)(g + j4 * 128 + lane * 4));
            float4 lv = *(const float4*)(La_s + j4 * 128 + lane * 4);
            v[j4 * 4 + 0] = f2ord(lv.x + gv.x);
            v[j4 * 4 + 1] = f2ord(lv.y + gv.y);
            v[j4 * 4 + 2] = f2ord(lv.z + gv.z);
            v[j4 * 4 + 3] = f2ord(lv.w + gv.w);
        }
        int gidx = 0;
        unsigned sel = warp_select32<true>(v, lane, &gidx);
        float* o = out + (size_t)row * 2048;
#pragma unroll
        for (int j4 = 0; j4 < 8; j4++) {
            float4 ov;
            ov.x = ((sel >> (j4 * 4 + 0)) & 1) ? 1.f : 0.f;
            ov.y = ((sel >> (j4 * 4 + 1)) & 1) ? 1.f : 0.f;
            ov.z = ((sel >> (j4 * 4 + 2)) & 1) ? 1.f : 0.f;
            ov.w = ((sel >> (j4 * 4 + 3)) & 1) ? 1.f : 0.f;
            *(float4*)(o + j4 * 128 + lane * 4) = ov;
        }
        // ctx = bc + sum of selected Wc rows
        float acc = __ldg(bc + lane);
#pragma unroll
        for (int k = 0; k < 32; k++) {
            int idx = __shfl_sync(FULLMASK, gidx, k);
            acc += __ldg(Wc + (size_t)idx * 32 + lane);
        }
        ctx_s[rr * 32 + lane] = acc;
    }
    __syncthreads();

    int r = t >> 4, s = t & 15;
    // ---- layer 1 (W1b ctx-slice from smem; base_b part folded into d_c1) ----
    {
        float acc[8];
#pragma unroll
        for (int k = 0; k < 8; k++) acc[k] = d_c1[s + 16 * k];
        for (int i = 0; i < 32; i++) {
            float cv = ctx_s[r * 32 + i];
#pragma unroll
            for (int k = 0; k < 8; k++) acc[k] += cv * wbuf[i * 128 + s + 16 * k];
        }
#pragma unroll
        for (int k = 0; k < 8; k++) h1s[r * 128 + s + 16 * k] = leaky(acc[k]);
    }
    __syncthreads();
    // ---- layer 2 (W2b from smem) ----
    {
        const float* w2 = wbuf + 4096;
        float acc[4];
#pragma unroll
        for (int k = 0; k < 4; k++) acc[k] = __ldg(&b2b[s + 16 * k]);
        for (int i = 0; i < 128; i++) {
            float hv = h1s[r * 128 + i];
#pragma unroll
            for (int k = 0; k < 4; k++) acc[k] += hv * w2[i * 64 + s + 16 * k];
        }
#pragma unroll
        for (int k = 0; k < 4; k++) h2t[(s + 16 * k) * 16 + r] = leaky(acc[k]);
    }
    __syncthreads();  // h2t ready; wbuf (W1b/W2b) dead -> reusable as lg
    // ---- layer 3: thread owns 4 outputs x 16 rows, rows paired in f32x2 ----
    {
        int o0 = t * 4;
        unsigned long long acc[32];
#pragma unroll
        for (int z = 0; z < 32; z++) acc[z] = 0ull;
#pragma unroll 4
        for (int i = 0; i < 64; i++) {
            float4 wv = __ldg((const float4*)(W3b + i * 1024 + o0));
            unsigned long long w0 = pack2(wv.x, wv.x);
            unsigned long long w1 = pack2(wv.y, wv.y);
            unsigned long long w2p = pack2(wv.z, wv.z);
            unsigned long long w3 = pack2(wv.w, wv.w);
            const float2* hp = (const float2*)(h2t + i * 16);
#pragma unroll
            for (int rp = 0; rp < 8; rp++) {
                float2 h = hp[rp];
                unsigned long long hh = pack2(h.x, h.y);
                acc[rp * 4 + 0] = fma2(w0, hh, acc[rp * 4 + 0]);
                acc[rp * 4 + 1] = fma2(w1, hh, acc[rp * 4 + 1]);
                acc[rp * 4 + 2] = fma2(w2p, hh, acc[rp * 4 + 2]);
                acc[rp * 4 + 3] = fma2(w3, hh, acc[rp * 4 + 3]);
            }
        }
        float bq[4];
#pragma unroll
        for (int q = 0; q < 4; q++) bq[q] = __ldg(&b3b[o0 + q]) + __ldg(&baseline_b[o0 + q]);
#pragma unroll
        for (int rp = 0; rp < 8; rp++) {
            float lo0, hi0, lo1, hi1, lo2, hi2, lo3, hi3;
            unpack2(acc[rp * 4 + 0], lo0, hi0);
            unpack2(acc[rp * 4 + 1], lo1, hi1);
            unpack2(acc[rp * 4 + 2], lo2, hi2);
            unpack2(acc[rp * 4 + 3], lo3, hi3);
            *(float4*)(lg + (rp * 2) * 1024 + o0) =
                make_float4(lo0 + bq[0], lo1 + bq[1], lo2 + bq[2], lo3 + bq[3]);
            *(float4*)(lg + (rp * 2 + 1) * 1024 + o0) =
                make_float4(hi0 + bq[0], hi1 + bq[1], hi2 + bq[2], hi3 + bq[3]);
        }
    }
    __syncthreads();
    // ---- beta selection: 2 rows per warp ----
#pragma unroll 1
    for (int rr = w * 2; rr < w * 2 + 2; rr++) {
        int row = row0 + rr;
        if (row >= B) continue;
        const float* g = g_beta + (size_t)row * 1024;
        unsigned v[32];
#pragma unroll
        for (int j4 = 0; j4 < 8; j4++) {
            float4 gv = __ldg((const float4*)(g + j4 * 128 + lane * 4));
            float4 lv = *(const float4*)(lg + rr * 1024 + j4 * 128 + lane * 4);
            v[j4 * 4 + 0] = f2ord(lv.x + gv.x);
            v[j4 * 4 + 1] = f2ord(lv.y + gv.y);
            v[j4 * 4 + 2] = f2ord(lv.z + gv.z);
            v[j4 * 4 + 3] = f2ord(lv.w + gv.w);
        }
        int dummy;
        unsigned sel = warp_select32<false>(v, lane, &dummy);
        float* o = out + (size_t)row * 2048 + 1024;
#pragma unroll
        for (int j4 = 0; j4 < 8; j4++) {
            float4 ov;
            ov.x = ((sel >> (j4 * 4 + 0)) & 1) ? 1.f : 0.f;
            ov.y = ((sel >> (j4 * 4 + 1)) & 1) ? 1.f : 0.f;
            ov.z = ((sel >> (j4 * 4 + 2)) & 1) ? 1.f : 0.f;
            ov.w = ((sel >> (j4 * 4 + 3)) & 1) ? 1.f : 0.f;
            *(float4*)(o + j4 * 128 + lane * 4) = ov;
        }
    }
}

// ---------------- launcher ----------------
extern "C" void kernel_launch(void* const* d_in, const int* in_sizes, int n_in,
                              void* d_out, int out_size) {
    const float* baseline_a = (const float*)d_in[0];
    const float* W1a = (const float*)d_in[1];
    const float* b1a = (const float*)d_in[2];
    const float* W2a = (const float*)d_in[3];
    const float* b2a = (const float*)d_in[4];
    const float* W3a = (const float*)d_in[5];
    const float* b3a = (const float*)d_in[6];
    const float* baseline_b = (const float*)d_in[7];
    const float* Wc  = (const float*)d_in[8];
    const float* bc  = (const float*)d_in[9];
    const float* W1b = (const float*)d_in[10];
    const float* b1b = (const float*)d_in[11];
    const float* W2b = (const float*)d_in[12];
    const float* b2b = (const float*)d_in[13];
    const float* W3b = (const float*)d_in[14];
    const float* b3b = (const float*)d_in[15];
    const float* g_alpha = (const float*)d_in[16];
    const float* g_beta  = (const float*)d_in[17];
    float* out = (float*)d_out;

    int B = in_sizes[16] / 1024;
    if (B <= 0) return;

    cudaFuncSetAttribute(kmain, cudaFuncAttributeMaxDynamicSharedMemorySize, 86016);

    kp1<<<64, 256>>>(baseline_a, W1a, baseline_b, W1b);
    kp2<<<1, 256>>>(b1a, b1b, W2a, b2a);
    kp3<<<8, 128>>>(W3a, b3a, baseline_a);
    kmain<<<(B + 15) / 16, 256, SMEM_FLOATS * sizeof(float)>>>(
        g_alpha, g_beta, Wc, bc, W1b, W2b, b2b, W3b, b3b, baseline_b, out, B);
}